// round 1
// baseline (speedup 1.0000x reference)
#include <cuda_runtime.h>
#include <math.h>

#define BB 4
#define LL 2048
#define CC 1024
#define C3 3072

// Scratch (device globals are the sanctioned scratch mechanism)
__device__ float g_qkv[(size_t)BB * LL * C3];   // 96 MB: q|k|v concatenated per row
__device__ float g_attn[(size_t)BB * LL * LL];  // 64 MB: scores -> probs (in place)
__device__ float g_o[(size_t)BB * LL * CC];     // 32 MB: attention output

#define TM 128
#define TN 128
#define TK 16

// Shared GEMM tile body.
// BT=true:  C[m,n] = scale * sum_k A[m,k] * B[n,k]   (both K-contiguous)
// BT=false: C[m,n] = scale * sum_k A[m,k] * B[k,n]
// MASK: causal mask in epilogue (col > row -> -inf)
template <bool BT, bool MASK>
__device__ __forceinline__ void gemm_tile(const float* __restrict__ A,
                                          const float* __restrict__ B,
                                          float* __restrict__ Cout,
                                          int Ksz, int lda, int ldb, int ldc,
                                          int m0, int n0, float scale)
{
    __shared__ float As[TK][TM];
    __shared__ float Bs[TK][TN];
    const int tid = threadIdx.x;       // 0..255
    const int tx = tid & 15;
    const int ty = tid >> 4;

    float acc[8][8];
#pragma unroll
    for (int i = 0; i < 8; i++)
#pragma unroll
        for (int j = 0; j < 8; j++) acc[i][j] = 0.f;

    for (int k0 = 0; k0 < Ksz; k0 += TK) {
#pragma unroll
        for (int it = 0; it < 2; ++it) {
            int idx = tid + it * 256;            // 0..511
            {   // A tile: 128 rows x 16 k, transpose into As[k][m]
                int r = idx >> 2;
                int c = (idx & 3) << 2;
                float4 v = *(const float4*)(A + (size_t)(m0 + r) * lda + k0 + c);
                As[c + 0][r] = v.x; As[c + 1][r] = v.y;
                As[c + 2][r] = v.z; As[c + 3][r] = v.w;
            }
            if (BT) {   // B tile: 128 n-rows x 16 k, transpose into Bs[k][n]
                int r = idx >> 2;
                int c = (idx & 3) << 2;
                float4 v = *(const float4*)(B + (size_t)(n0 + r) * ldb + k0 + c);
                Bs[c + 0][r] = v.x; Bs[c + 1][r] = v.y;
                Bs[c + 2][r] = v.z; Bs[c + 3][r] = v.w;
            } else {    // B tile: 16 k-rows x 128 n, direct
                int r = idx >> 5;
                int c = (idx & 31) << 2;
                *(float4*)&Bs[r][c] =
                    *(const float4*)(B + (size_t)(k0 + r) * ldb + n0 + c);
            }
        }
        __syncthreads();
#pragma unroll
        for (int kk = 0; kk < TK; ++kk) {
            float a[8], b[8];
            *(float4*)&a[0] = *(const float4*)&As[kk][ty * 8];
            *(float4*)&a[4] = *(const float4*)&As[kk][ty * 8 + 4];
            *(float4*)&b[0] = *(const float4*)&Bs[kk][tx * 8];
            *(float4*)&b[4] = *(const float4*)&Bs[kk][tx * 8 + 4];
#pragma unroll
            for (int i = 0; i < 8; i++)
#pragma unroll
                for (int j = 0; j < 8; j++)
                    acc[i][j] = fmaf(a[i], b[j], acc[i][j]);
        }
        __syncthreads();
    }

#pragma unroll
    for (int i = 0; i < 8; i++) {
        int row = m0 + ty * 8 + i;
#pragma unroll
        for (int jv = 0; jv < 2; jv++) {
            int col = n0 + tx * 8 + jv * 4;
            float4 v;
            v.x = acc[i][jv * 4 + 0] * scale;
            v.y = acc[i][jv * 4 + 1] * scale;
            v.z = acc[i][jv * 4 + 2] * scale;
            v.w = acc[i][jv * 4 + 3] * scale;
            if (MASK) {
                if (col + 0 > row) v.x = -INFINITY;
                if (col + 1 > row) v.y = -INFINITY;
                if (col + 2 > row) v.z = -INFINITY;
                if (col + 3 > row) v.w = -INFINITY;
            }
            *(float4*)(Cout + (size_t)row * ldc + col) = v;
        }
    }
}

// Stage 1: qkv[m, d] = sum_c x[m,c] * w_qkv[d,c]    (m = b*L + l, 8192 x 3072 x 1024)
__global__ void __launch_bounds__(256) qkv_kernel(const float* __restrict__ x,
                                                  const float* __restrict__ w)
{
    gemm_tile<true, false>(x, w, g_qkv, CC, CC, CC, C3,
                           blockIdx.y * TM, blockIdx.x * TN, 1.f);
}

// Stage 2: S[b,q,k] = (q . k)/32, causal-masked; upper-triangle blocks skipped
__global__ void __launch_bounds__(256) score_kernel()
{
    int b = blockIdx.z;
    int m0 = blockIdx.y * TM, n0 = blockIdx.x * TN;
    if (n0 > m0 + (TM - 1)) return;               // fully masked block: never read
    const float* Q  = g_qkv + (size_t)b * LL * C3;
    const float* Kp = Q + CC;
    float* S = g_attn + (size_t)b * LL * LL;
    gemm_tile<true, true>(Q, Kp, S, CC, C3, C3, LL, m0, n0, 0.03125f);
}

// Stage 3: per-row causal softmax over k in [0, roundup(q+1,128))
__global__ void __launch_bounds__(256) softmax_kernel()
{
    int q = blockIdx.x, b = blockIdx.y;
    float* row = g_attn + ((size_t)b * LL + q) * LL;
    int kend = ((q >> 7) + 1) << 7;               // multiple of 128, >= q+1
    int tid = threadIdx.x;

    float v[8];
#pragma unroll
    for (int i = 0; i < 8; i++) {
        int k = tid + i * 256;
        v[i] = (k < kend) ? row[k] : -INFINITY;
    }
    float m = -INFINITY;
#pragma unroll
    for (int i = 0; i < 8; i++) m = fmaxf(m, v[i]);

    __shared__ float sred[8];
#pragma unroll
    for (int o = 16; o; o >>= 1) m = fmaxf(m, __shfl_xor_sync(0xffffffffu, m, o));
    if ((tid & 31) == 0) sred[tid >> 5] = m;
    __syncthreads();
    if (tid < 32) {
        float x = (tid < 8) ? sred[tid] : -INFINITY;
#pragma unroll
        for (int o = 4; o; o >>= 1) x = fmaxf(x, __shfl_xor_sync(0xffffffffu, x, o));
        if (tid == 0) sred[0] = x;
    }
    __syncthreads();
    m = sred[0];
    __syncthreads();

    float s = 0.f;
#pragma unroll
    for (int i = 0; i < 8; i++) { v[i] = expf(v[i] - m); s += v[i]; }
#pragma unroll
    for (int o = 16; o; o >>= 1) s += __shfl_xor_sync(0xffffffffu, s, o);
    if ((tid & 31) == 0) sred[tid >> 5] = s;
    __syncthreads();
    if (tid < 32) {
        float x = (tid < 8) ? sred[tid] : 0.f;
#pragma unroll
        for (int o = 4; o; o >>= 1) x += __shfl_xor_sync(0xffffffffu, x, o);
        if (tid == 0) sred[0] = x;
    }
    __syncthreads();
    float inv = 1.0f / sred[0];
#pragma unroll
    for (int i = 0; i < 8; i++) {
        int k = tid + i * 256;
        if (k < kend) row[k] = v[i] * inv;
    }
}

// Stage 4: O[b,q,c] = sum_k P[b,q,k] * v[b,k,c]; K-loop truncated at m0+128 (causal)
__global__ void __launch_bounds__(256) pv_kernel()
{
    int b = blockIdx.z;
    int m0 = blockIdx.y * TM, n0 = blockIdx.x * TN;
    const float* P = g_attn + (size_t)b * LL * LL;
    const float* V = g_qkv + (size_t)b * LL * C3 + 2 * CC;
    float* O = g_o + (size_t)b * LL * CC;
    gemm_tile<false, false>(P, V, O, m0 + TM, LL, C3, CC, m0, n0, 1.f);
}

// Stage 5: y[m, d] = sum_c O[m,c] * w_out[d,c]
__global__ void __launch_bounds__(256) out_kernel(const float* __restrict__ w,
                                                  float* __restrict__ y)
{
    gemm_tile<true, false>(g_o, w, y, CC, CC, CC, CC,
                           blockIdx.y * TM, blockIdx.x * TN, 1.f);
}

extern "C" void kernel_launch(void* const* d_in, const int* in_sizes, int n_in,
                              void* d_out, int out_size)
{
    const float* x     = (const float*)d_in[0];
    const float* w_qkv = (const float*)d_in[1];
    const float* w_out = (const float*)d_in[2];
    float* y = (float*)d_out;

    qkv_kernel<<<dim3(C3 / TN, (BB * LL) / TM), 256>>>(x, w_qkv);
    score_kernel<<<dim3(LL / TN, LL / TM, BB), 256>>>();
    softmax_kernel<<<dim3(LL, BB), 256>>>();
    pv_kernel<<<dim3(CC / TN, LL / TM, BB), 256>>>();
    out_kernel<<<dim3(CC / TN, (BB * LL) / TM), 256>>>(w_out, y);
}

// round 3
// speedup vs baseline: 3.2411x; 3.2411x over previous
#include <cuda_runtime.h>
#include <math.h>
#include <stdint.h>

#define BB 4
#define LL 2048
#define CC 1024
#define C3 3072

// Scratch (device globals are the sanctioned scratch mechanism)
__device__ float g_qkv[(size_t)BB * LL * C3];   // 96 MB
__device__ float g_attn[(size_t)BB * LL * LL];  // 64 MB
__device__ float g_o[(size_t)BB * LL * CC];     // 32 MB

// ---------------- helpers ----------------
__device__ __forceinline__ uint32_t smem_u32(const void* p) {
    uint32_t a;
    asm("{ .reg .u64 t; cvta.to.shared.u64 t, %1; cvt.u32.u64 %0, t; }" : "=r"(a) : "l"(p));
    return a;
}
__device__ __forceinline__ uint32_t f2tf(float f) {  // fp32 -> tf32, round-to-nearest
    uint32_t r;
    asm("cvt.rna.tf32.f32 %0, %1;" : "=r"(r) : "f"(f));
    return r;
}
__device__ __forceinline__ void ldsm4(uint32_t (&r)[4], uint32_t addr) {
    asm volatile("ldmatrix.sync.aligned.m8n8.x4.shared.b16 {%0,%1,%2,%3}, [%4];"
                 : "=r"(r[0]), "=r"(r[1]), "=r"(r[2]), "=r"(r[3]) : "r"(addr));
}
__device__ __forceinline__ void mma_tf32(float (&d)[4], const uint32_t (&a)[4],
                                         const uint32_t b0, const uint32_t b1) {
    asm volatile("mma.sync.aligned.m16n8k8.row.col.f32.tf32.tf32.f32 "
                 "{%0,%1,%2,%3}, {%4,%5,%6,%7}, {%8,%9}, {%0,%1,%2,%3};"
                 : "+f"(d[0]), "+f"(d[1]), "+f"(d[2]), "+f"(d[3])
                 : "r"(a[0]), "r"(a[1]), "r"(a[2]), "r"(a[3]), "r"(b0), "r"(b1));
}

#define STS128U(addr, a, b, c, d) \
    asm volatile("st.shared.v4.b32 [%0], {%1,%2,%3,%4};" :: "r"(addr), "r"(a), "r"(b), "r"(c), "r"(d) : "memory")

// SMEM tile geometry: 128 rows x 16 k-floats, row stride 20 floats (80 bytes).
// 80 = 5*16 -> 8 consecutive rows hit 8 distinct 16B granules mod 128B:
// conflict-free ldmatrix and conflict-free quarter-warp float4 STS.
#define ROWF 20
#define TILEF (128 * ROWF)   // 2560 floats = 10240 B per buffer

// ---------------- tf32 mma.sync GEMM tile ----------------
// C[m0..+128, n0..+128] = scale * A(128xK, row-major lda) . B^T
// BNM=false: B row-major [n][k] (k contiguous), n rows at n0.
// BNM=true : B is [k][n] (n contiguous) e.g. V; loaded untransposed, scalar-LDS frags.
// MASK: causal -inf where col > row (epilogue).
template <bool BNM, bool MASK>
__device__ __forceinline__ void tc_gemm(const float* __restrict__ A, int lda,
                                        const float* __restrict__ B, int ldb,
                                        float* __restrict__ C, int ldc,
                                        int Ksz, int m0, int n0, float scale)
{
    __shared__ float sA[2][TILEF];
    __shared__ float sB[2][TILEF];   // BNM=true uses it as [16][132] (2112 <= 2560)

    const int tid = threadIdx.x;
    const int ln = tid & 31, wid = tid >> 5;
    const int wm = wid >> 2, wn = wid & 3;     // warp tile origin (wm*64, wn*32)
    const int gid = ln >> 2, tig = ln & 3;

    const uint32_t sAu = smem_u32(sA);
    const uint32_t sBu = smem_u32(sB);

    // gmem<->smem coords (items tid and tid+256)
    const int rA = tid >> 2, cA = tid & 3;          // A & B-kmajor: rows rA, rA+64
    const int kkB = tid >> 5, cB = tid & 31;        // B-nmajor: k rows kkB, kkB+8

    // ldmatrix invariant address pieces
    const int rowAf = wm * 64 + (ln & 7) + ((ln >> 3) & 1) * 8;
    const int colA16 = ln >> 4;                     // 0/1 -> k 16B half
    const int rowBf = wn * 32 + (ln & 7) + ((ln >> 4) & 1) * 8;
    const int colB16 = (ln >> 3) & 1;

    float acc[4][4][4];
#pragma unroll
    for (int i = 0; i < 4; i++)
#pragma unroll
        for (int j = 0; j < 4; j++)
#pragma unroll
            for (int e = 0; e < 4; e++) acc[i][j][e] = 0.f;

    float4 va[2], vb[2];
    const int nch = Ksz >> 4;

    // ---- prologue: chunk 0 ----
#pragma unroll
    for (int i = 0; i < 2; i++)
        va[i] = *(const float4*)(A + (size_t)(m0 + rA + 64 * i) * lda + cA * 4);
    if (!BNM) {
#pragma unroll
        for (int i = 0; i < 2; i++)
            vb[i] = *(const float4*)(B + (size_t)(n0 + rA + 64 * i) * ldb + cA * 4);
    } else {
#pragma unroll
        for (int i = 0; i < 2; i++)
            vb[i] = *(const float4*)(B + (size_t)(kkB + 8 * i) * ldb + n0 + cB * 4);
    }
    {
        const uint32_t a0 = sAu;
        const uint32_t b0a = sBu;
#pragma unroll
        for (int i = 0; i < 2; i++) {
            uint32_t off = (uint32_t)(((rA + 64 * i) * ROWF + cA * 4) * 4);
            STS128U(a0 + off, f2tf(va[i].x), f2tf(va[i].y), f2tf(va[i].z), f2tf(va[i].w));
        }
        if (!BNM) {
#pragma unroll
            for (int i = 0; i < 2; i++) {
                uint32_t off = (uint32_t)(((rA + 64 * i) * ROWF + cA * 4) * 4);
                STS128U(b0a + off, f2tf(vb[i].x), f2tf(vb[i].y), f2tf(vb[i].z), f2tf(vb[i].w));
            }
        } else {
#pragma unroll
            for (int i = 0; i < 2; i++) {
                uint32_t off = (uint32_t)(((kkB + 8 * i) * 132 + cB * 4) * 4);
                STS128U(b0a + off, f2tf(vb[i].x), f2tf(vb[i].y), f2tf(vb[i].z), f2tf(vb[i].w));
            }
        }
    }
    __syncthreads();

    for (int c = 0; c < nch; ++c) {
        const int s = c & 1;
        const bool more = (c + 1) < nch;
        if (more) {
            const int k0 = (c + 1) << 4;
#pragma unroll
            for (int i = 0; i < 2; i++)
                va[i] = *(const float4*)(A + (size_t)(m0 + rA + 64 * i) * lda + k0 + cA * 4);
            if (!BNM) {
#pragma unroll
                for (int i = 0; i < 2; i++)
                    vb[i] = *(const float4*)(B + (size_t)(n0 + rA + 64 * i) * ldb + k0 + cA * 4);
            } else {
#pragma unroll
                for (int i = 0; i < 2; i++)
                    vb[i] = *(const float4*)(B + (size_t)(k0 + kkB + 8 * i) * ldb + n0 + cB * 4);
            }
        }

        // ---- compute on buffer s (two k8 sub-steps) ----
        const uint32_t aBase = sAu + (uint32_t)(s * TILEF * 4);
        const uint32_t bBase = sBu + (uint32_t)(s * TILEF * 4);
#pragma unroll
        for (int k8 = 0; k8 < 2; ++k8) {
            uint32_t af[4][4];
#pragma unroll
            for (int i = 0; i < 4; i++)
                ldsm4(af[i], aBase + (uint32_t)((((rowAf + i * 16) * ROWF) + k8 * 8 + colA16 * 4) * 4));

            uint32_t bf[4][2];
            if (!BNM) {
#pragma unroll
                for (int p = 0; p < 2; ++p) {
                    uint32_t q[4];
                    ldsm4(q, bBase + (uint32_t)((((rowBf + p * 16) * ROWF) + k8 * 8 + colB16 * 4) * 4));
                    bf[2 * p][0] = q[0]; bf[2 * p][1] = q[1];
                    bf[2 * p + 1][0] = q[2]; bf[2 * p + 1][1] = q[3];
                }
            } else {
                const float* bs = sB[s];
#pragma unroll
                for (int j = 0; j < 4; ++j) {
                    int n = wn * 32 + j * 8 + gid;
                    bf[j][0] = __float_as_uint(bs[(k8 * 8 + tig) * 132 + n]);
                    bf[j][1] = __float_as_uint(bs[(k8 * 8 + tig + 4) * 132 + n]);
                }
            }
#pragma unroll
            for (int i = 0; i < 4; i++)
#pragma unroll
                for (int j = 0; j < 4; j++)
                    mma_tf32(acc[i][j], af[i], bf[j][0], bf[j][1]);
        }

        if (more) {
            const uint32_t a1 = sAu + (uint32_t)(((c + 1) & 1) * TILEF * 4);
            const uint32_t b1 = sBu + (uint32_t)(((c + 1) & 1) * TILEF * 4);
#pragma unroll
            for (int i = 0; i < 2; i++) {
                uint32_t off = (uint32_t)(((rA + 64 * i) * ROWF + cA * 4) * 4);
                STS128U(a1 + off, f2tf(va[i].x), f2tf(va[i].y), f2tf(va[i].z), f2tf(va[i].w));
            }
            if (!BNM) {
#pragma unroll
                for (int i = 0; i < 2; i++) {
                    uint32_t off = (uint32_t)(((rA + 64 * i) * ROWF + cA * 4) * 4);
                    STS128U(b1 + off, f2tf(vb[i].x), f2tf(vb[i].y), f2tf(vb[i].z), f2tf(vb[i].w));
                }
            } else {
#pragma unroll
                for (int i = 0; i < 2; i++) {
                    uint32_t off = (uint32_t)(((kkB + 8 * i) * 132 + cB * 4) * 4);
                    STS128U(b1 + off, f2tf(vb[i].x), f2tf(vb[i].y), f2tf(vb[i].z), f2tf(vb[i].w));
                }
            }
        }
        __syncthreads();
    }

    // ---- epilogue: registers -> gmem (float2 stores) ----
#pragma unroll
    for (int i = 0; i < 4; i++) {
        const int row0 = m0 + wm * 64 + i * 16 + gid;
#pragma unroll
        for (int j = 0; j < 4; j++) {
            const int col = n0 + wn * 32 + j * 8 + 2 * tig;
            float2 v0, v1;
            v0.x = acc[i][j][0] * scale; v0.y = acc[i][j][1] * scale;
            v1.x = acc[i][j][2] * scale; v1.y = acc[i][j][3] * scale;
            if (MASK) {
                if (col > row0)         v0.x = -INFINITY;
                if (col + 1 > row0)     v0.y = -INFINITY;
                if (col > row0 + 8)     v1.x = -INFINITY;
                if (col + 1 > row0 + 8) v1.y = -INFINITY;
            }
            *(float2*)(C + (size_t)row0 * ldc + col) = v0;
            *(float2*)(C + (size_t)(row0 + 8) * ldc + col) = v1;
        }
    }
}

// ---------------- stage kernels ----------------
__global__ void __launch_bounds__(256, 2) k_qkv(const float* __restrict__ x,
                                                const float* __restrict__ w) {
    tc_gemm<false, false>(x, CC, w, CC, g_qkv, C3, CC,
                          blockIdx.y * 128, blockIdx.x * 128, 1.f);
}

__global__ void __launch_bounds__(256, 2) k_score() {
    const int b = blockIdx.z;
    const int m0 = blockIdx.y * 128, n0 = blockIdx.x * 128;
    if (n0 > m0) return;  // fully-masked block: never written, never read by softmax
    const float* Q = g_qkv + (size_t)b * LL * C3;
    tc_gemm<false, true>(Q, C3, Q + CC, C3, g_attn + (size_t)b * LL * LL, LL, CC,
                         m0, n0, 0.03125f);
}

__global__ void __launch_bounds__(256) softmax_kernel() {
    int q = blockIdx.x, b = blockIdx.y;
    float* row = g_attn + ((size_t)b * LL + q) * LL;
    int kend = ((q >> 7) + 1) << 7;
    int tid = threadIdx.x;

    float v[8];
#pragma unroll
    for (int i = 0; i < 8; i++) {
        int k = tid + i * 256;
        v[i] = (k < kend) ? row[k] : -INFINITY;
    }
    float m = -INFINITY;
#pragma unroll
    for (int i = 0; i < 8; i++) m = fmaxf(m, v[i]);

    __shared__ float sred[8];
#pragma unroll
    for (int o = 16; o; o >>= 1) m = fmaxf(m, __shfl_xor_sync(0xffffffffu, m, o));
    if ((tid & 31) == 0) sred[tid >> 5] = m;
    __syncthreads();
    if (tid < 32) {
        float x = (tid < 8) ? sred[tid] : -INFINITY;
#pragma unroll
        for (int o = 4; o; o >>= 1) x = fmaxf(x, __shfl_xor_sync(0xffffffffu, x, o));
        if (tid == 0) sred[0] = x;
    }
    __syncthreads();
    m = sred[0];
    __syncthreads();

    float s = 0.f;
#pragma unroll
    for (int i = 0; i < 8; i++) { v[i] = expf(v[i] - m); s += v[i]; }
#pragma unroll
    for (int o = 16; o; o >>= 1) s += __shfl_xor_sync(0xffffffffu, s, o);
    if ((tid & 31) == 0) sred[tid >> 5] = s;
    __syncthreads();
    if (tid < 32) {
        float x = (tid < 8) ? sred[tid] : 0.f;
#pragma unroll
        for (int o = 4; o; o >>= 1) x += __shfl_xor_sync(0xffffffffu, x, o);
        if (tid == 0) sred[0] = x;
    }
    __syncthreads();
    float inv = 1.0f / sred[0];
#pragma unroll
    for (int i = 0; i < 8; i++) {
        int k = tid + i * 256;
        if (k < kend) row[k] = v[i] * inv;
    }
}

__global__ void __launch_bounds__(256, 2) k_pv() {
    const int b = blockIdx.z;
    const int m0 = blockIdx.y * 128, n0 = blockIdx.x * 128;
    const float* P = g_attn + (size_t)b * LL * LL;
    const float* V = g_qkv + (size_t)b * LL * C3 + 2 * CC;
    tc_gemm<true, false>(P, LL, V, C3, g_o + (size_t)b * LL * CC, CC,
                         m0 + 128 /* causal K truncation */, m0, n0, 1.f);
}

__global__ void __launch_bounds__(256, 2) k_out(const float* __restrict__ w,
                                                float* __restrict__ y) {
    tc_gemm<false, false>(g_o, CC, w, CC, y, CC, CC,
                          blockIdx.y * 128, blockIdx.x * 128, 1.f);
}

extern "C" void kernel_launch(void* const* d_in, const int* in_sizes, int n_in,
                              void* d_out, int out_size)
{
    const float* x     = (const float*)d_in[0];
    const float* w_qkv = (const float*)d_in[1];
    const float* w_out = (const float*)d_in[2];
    float* y = (float*)d_out;

    k_qkv<<<dim3(C3 / 128, (BB * LL) / 128), 256>>>(x, w_qkv);
    k_score<<<dim3(LL / 128, LL / 128, BB), 256>>>();
    softmax_kernel<<<dim3(LL, BB), 256>>>();
    k_pv<<<dim3(CC / 128, LL / 128, BB), 256>>>();
    k_out<<<dim3(CC / 128, (BB * LL) / 128), 256>>>(w_out, y);
}

// round 4
// speedup vs baseline: 3.2827x; 1.0128x over previous
#include <cuda_runtime.h>
#include <math.h>
#include <stdint.h>

#define BB 4
#define LL 2048
#define CC 1024
#define C3 3072

// Scratch (device globals are the sanctioned scratch mechanism)
__device__ float g_qkv[(size_t)BB * LL * C3];   // 96 MB
__device__ float g_attn[(size_t)BB * LL * LL];  // 64 MB
__device__ float g_o[(size_t)BB * LL * CC];     // 32 MB

// ---------------- helpers ----------------
__device__ __forceinline__ uint32_t smem_u32(const void* p) {
    uint32_t a;
    asm("{ .reg .u64 t; cvta.to.shared.u64 t, %1; cvt.u32.u64 %0, t; }" : "=r"(a) : "l"(p));
    return a;
}
__device__ __forceinline__ uint32_t f2tf(float f) {  // fp32 -> tf32, round-to-nearest
    uint32_t r;
    asm("cvt.rna.tf32.f32 %0, %1;" : "=r"(r) : "f"(f));
    return r;
}
__device__ __forceinline__ void ldsm4(uint32_t (&r)[4], uint32_t addr) {
    asm volatile("ldmatrix.sync.aligned.m8n8.x4.shared.b16 {%0,%1,%2,%3}, [%4];"
                 : "=r"(r[0]), "=r"(r[1]), "=r"(r[2]), "=r"(r[3]) : "r"(addr));
}
__device__ __forceinline__ void mma_tf32(float (&d)[4], const uint32_t (&a)[4],
                                         const uint32_t b0, const uint32_t b1) {
    asm volatile("mma.sync.aligned.m16n8k8.row.col.f32.tf32.tf32.f32 "
                 "{%0,%1,%2,%3}, {%4,%5,%6,%7}, {%8,%9}, {%0,%1,%2,%3};"
                 : "+f"(d[0]), "+f"(d[1]), "+f"(d[2]), "+f"(d[3])
                 : "r"(a[0]), "r"(a[1]), "r"(a[2]), "r"(a[3]), "r"(b0), "r"(b1));
}

#define STS128U(addr, a, b, c, d) \
    asm volatile("st.shared.v4.b32 [%0], {%1,%2,%3,%4};" :: "r"(addr), "r"(a), "r"(b), "r"(c), "r"(d) : "memory")

// k32 chunk, double-buffered. K-major rows stride 36 floats (144B = 9 granules:
// 9 mod 8 = 1 -> 8 consecutive rows hit 8 distinct 16B granules: conflict-free ldmatrix).
// BNM B-tile stored [k][n] stride 136 floats (136 mod 32 = 8 -> conflict-free scalar LDS).
#define RS      36
#define TILEF   (128 * RS)            // 4608 floats per matrix per stage
#define STAGEF  (2 * TILEF)           // A then B
#define SMEM_DYN (2 * STAGEF * 4)     // 73728 bytes
#define BNM_RS  136

// ---------------- tf32 mma.sync GEMM tile ----------------
// C[m0..+128, n0..+128] = scale * A(128xK, row-major lda) . B^T
// BNM=false: B row-major [n][k] (k contiguous), n rows at n0.
// BNM=true : B is [k][n] (n contiguous) e.g. V; loaded untransposed, scalar-LDS frags.
// MASK: causal -inf where col > row (epilogue). Ksz must be a multiple of 32.
template <bool BNM, bool MASK>
__device__ __forceinline__ void tc_gemm(const float* __restrict__ A, int lda,
                                        const float* __restrict__ B, int ldb,
                                        float* __restrict__ C, int ldc,
                                        int Ksz, int m0, int n0, float scale)
{
    extern __shared__ __align__(16) float dsm[];
    const uint32_t sb = smem_u32(dsm);

    const int tid = threadIdx.x;
    const int ln = tid & 31, wid = tid >> 5;
    const int wm = wid >> 2, wn = wid & 3;     // warp tile origin (wm*64, wn*32)
    const int gid = ln >> 2, tig = ln & 3;

    // gmem<->smem coords
    const int rA = tid >> 2, cA = tid & 3;     // K-major: rows rA, rA+64; 4-float col group
    const int kkB = tid >> 5, cB = tid & 31;   // BNM: k rows kkB, kkB+8; 4-float col group

    // ldmatrix invariant pieces
    const int rowAf = wm * 64 + (ln & 7) + ((ln >> 3) & 1) * 8;
    const int colA16 = ln >> 4;
    const int rowBf = wn * 32 + (ln & 7) + ((ln >> 4) & 1) * 8;
    const int colB16 = (ln >> 3) & 1;

    float acc[4][4][4];
#pragma unroll
    for (int i = 0; i < 4; i++)
#pragma unroll
        for (int j = 0; j < 4; j++)
#pragma unroll
            for (int e = 0; e < 4; e++) acc[i][j][e] = 0.f;

    float4 va[2], vb[2];

    // ---- load helpers (k16-half granularity; h16 = k offset of the half) ----
    auto ldgA = [&](int h16) {
#pragma unroll
        for (int i = 0; i < 2; i++)
            va[i] = *(const float4*)(A + (size_t)(m0 + rA + 64 * i) * lda + h16 + cA * 4);
    };
    auto ldgB = [&](int h16) {
        if (!BNM) {
#pragma unroll
            for (int i = 0; i < 2; i++)
                vb[i] = *(const float4*)(B + (size_t)(n0 + rA + 64 * i) * ldb + h16 + cA * 4);
        } else {
#pragma unroll
            for (int i = 0; i < 2; i++)
                vb[i] = *(const float4*)(B + (size_t)(h16 + kkB + 8 * i) * ldb + n0 + cB * 4);
        }
    };
    auto stsAB = [&](int s, int hh /*0 or 16, k offset within chunk*/) {
        const uint32_t aB = sb + (uint32_t)(s * STAGEF * 4);
        const uint32_t bB = aB + (uint32_t)(TILEF * 4);
#pragma unroll
        for (int i = 0; i < 2; i++) {
            uint32_t off = (uint32_t)(((rA + 64 * i) * RS + hh + cA * 4) * 4);
            STS128U(aB + off, f2tf(va[i].x), f2tf(va[i].y), f2tf(va[i].z), f2tf(va[i].w));
        }
        if (!BNM) {
#pragma unroll
            for (int i = 0; i < 2; i++) {
                uint32_t off = (uint32_t)(((rA + 64 * i) * RS + hh + cA * 4) * 4);
                STS128U(bB + off, f2tf(vb[i].x), f2tf(vb[i].y), f2tf(vb[i].z), f2tf(vb[i].w));
            }
        } else {
#pragma unroll
            for (int i = 0; i < 2; i++) {
                uint32_t off = (uint32_t)(((hh + kkB + 8 * i) * BNM_RS + cB * 4) * 4);
                STS128U(bB + off, f2tf(vb[i].x), f2tf(vb[i].y), f2tf(vb[i].z), f2tf(vb[i].w));
            }
        }
    };
    auto compute_k8 = [&](int s, int q) {
        const uint32_t aB = sb + (uint32_t)(s * STAGEF * 4);
        const uint32_t bB = aB + (uint32_t)(TILEF * 4);
        uint32_t af[4][4];
#pragma unroll
        for (int i = 0; i < 4; i++)
            ldsm4(af[i], aB + (uint32_t)((((rowAf + i * 16) * RS) + q * 8 + colA16 * 4) * 4));
        uint32_t bf[4][2];
        if (!BNM) {
#pragma unroll
            for (int p = 0; p < 2; ++p) {
                uint32_t qq[4];
                ldsm4(qq, bB + (uint32_t)((((rowBf + p * 16) * RS) + q * 8 + colB16 * 4) * 4));
                bf[2 * p][0] = qq[0]; bf[2 * p][1] = qq[1];
                bf[2 * p + 1][0] = qq[2]; bf[2 * p + 1][1] = qq[3];
            }
        } else {
            const float* bs = dsm + s * STAGEF + TILEF;
#pragma unroll
            for (int j = 0; j < 4; ++j) {
                int n = wn * 32 + j * 8 + gid;
                bf[j][0] = __float_as_uint(bs[(q * 8 + tig) * BNM_RS + n]);
                bf[j][1] = __float_as_uint(bs[(q * 8 + tig + 4) * BNM_RS + n]);
            }
        }
#pragma unroll
        for (int i = 0; i < 4; i++)
#pragma unroll
            for (int j = 0; j < 4; j++)
                mma_tf32(acc[i][j], af[i], bf[j][0], bf[j][1]);
    };

    const int nch = Ksz >> 5;   // k32 chunks

    // ---- prologue: chunk 0 into stage 0 ----
#pragma unroll
    for (int h = 0; h < 2; h++) {
        ldgA(h * 16); ldgB(h * 16);
        stsAB(0, h * 16);
    }
    __syncthreads();

    for (int c = 0; c < nch; ++c) {
        const int s = c & 1;
        const bool more = (c + 1) < nch;
        const int k0n = (c + 1) << 5;

        if (more) { ldgA(k0n); ldgB(k0n); }
#pragma unroll
        for (int q = 0; q < 2; ++q) compute_k8(s, q);
        if (more) {
            stsAB(s ^ 1, 0);
            ldgA(k0n + 16); ldgB(k0n + 16);
        }
#pragma unroll
        for (int q = 2; q < 4; ++q) compute_k8(s, q);
        if (more) stsAB(s ^ 1, 16);
        __syncthreads();
    }

    // ---- epilogue: registers -> gmem (float2 stores) ----
#pragma unroll
    for (int i = 0; i < 4; i++) {
        const int row0 = m0 + wm * 64 + i * 16 + gid;
#pragma unroll
        for (int j = 0; j < 4; j++) {
            const int col = n0 + wn * 32 + j * 8 + 2 * tig;
            float2 v0, v1;
            v0.x = acc[i][j][0] * scale; v0.y = acc[i][j][1] * scale;
            v1.x = acc[i][j][2] * scale; v1.y = acc[i][j][3] * scale;
            if (MASK) {
                if (col > row0)         v0.x = -INFINITY;
                if (col + 1 > row0)     v0.y = -INFINITY;
                if (col > row0 + 8)     v1.x = -INFINITY;
                if (col + 1 > row0 + 8) v1.y = -INFINITY;
            }
            *(float2*)(C + (size_t)row0 * ldc + col) = v0;
            *(float2*)(C + (size_t)(row0 + 8) * ldc + col) = v1;
        }
    }
}

// ---------------- stage kernels ----------------
__global__ void __launch_bounds__(256, 2) k_qkv(const float* __restrict__ x,
                                                const float* __restrict__ w) {
    tc_gemm<false, false>(x, CC, w, CC, g_qkv, C3, CC,
                          blockIdx.y * 128, blockIdx.x * 128, 1.f);
}

__global__ void __launch_bounds__(256, 2) k_score() {
    const int b = blockIdx.z;
    const int m0 = blockIdx.y * 128, n0 = blockIdx.x * 128;
    if (n0 > m0) return;  // fully-masked block: never written, never read by softmax
    const float* Q = g_qkv + (size_t)b * LL * C3;
    tc_gemm<false, true>(Q, C3, Q + CC, C3, g_attn + (size_t)b * LL * LL, LL, CC,
                         m0, n0, 0.03125f);
}

__global__ void __launch_bounds__(256) softmax_kernel() {
    int q = blockIdx.x, b = blockIdx.y;
    float* row = g_attn + ((size_t)b * LL + q) * LL;
    int kend = ((q >> 7) + 1) << 7;
    int tid = threadIdx.x;

    float v[8];
#pragma unroll
    for (int i = 0; i < 8; i++) {
        int k = tid + i * 256;
        v[i] = (k < kend) ? row[k] : -INFINITY;
    }
    float m = -INFINITY;
#pragma unroll
    for (int i = 0; i < 8; i++) m = fmaxf(m, v[i]);

    __shared__ float sred[8];
#pragma unroll
    for (int o = 16; o; o >>= 1) m = fmaxf(m, __shfl_xor_sync(0xffffffffu, m, o));
    if ((tid & 31) == 0) sred[tid >> 5] = m;
    __syncthreads();
    if (tid < 32) {
        float x = (tid < 8) ? sred[tid] : -INFINITY;
#pragma unroll
        for (int o = 4; o; o >>= 1) x = fmaxf(x, __shfl_xor_sync(0xffffffffu, x, o));
        if (tid == 0) sred[0] = x;
    }
    __syncthreads();
    m = sred[0];
    __syncthreads();

    float s = 0.f;
#pragma unroll
    for (int i = 0; i < 8; i++) { v[i] = expf(v[i] - m); s += v[i]; }
#pragma unroll
    for (int o = 16; o; o >>= 1) s += __shfl_xor_sync(0xffffffffu, s, o);
    if ((tid & 31) == 0) sred[tid >> 5] = s;
    __syncthreads();
    if (tid < 32) {
        float x = (tid < 8) ? sred[tid] : 0.f;
#pragma unroll
        for (int o = 4; o; o >>= 1) x += __shfl_xor_sync(0xffffffffu, x, o);
        if (tid == 0) sred[0] = x;
    }
    __syncthreads();
    float inv = 1.0f / sred[0];
#pragma unroll
    for (int i = 0; i < 8; i++) {
        int k = tid + i * 256;
        if (k < kend) row[k] = v[i] * inv;
    }
}

__global__ void __launch_bounds__(256, 2) k_pv() {
    const int b = blockIdx.z;
    // longest-K tiles first (load balance: K = m0 + 128 grows with m0)
    const int by = gridDim.y - 1 - blockIdx.y;
    const int m0 = by * 128, n0 = blockIdx.x * 128;
    const float* P = g_attn + (size_t)b * LL * LL;
    const float* V = g_qkv + (size_t)b * LL * C3 + 2 * CC;
    tc_gemm<true, false>(P, LL, V, C3, g_o + (size_t)b * LL * CC, CC,
                         m0 + 128 /* causal K truncation */, m0, n0, 1.f);
}

__global__ void __launch_bounds__(256, 2) k_out(const float* __restrict__ w,
                                                float* __restrict__ y) {
    tc_gemm<false, false>(g_o, CC, w, CC, y, CC, CC,
                          blockIdx.y * 128, blockIdx.x * 128, 1.f);
}

extern "C" void kernel_launch(void* const* d_in, const int* in_sizes, int n_in,
                              void* d_out, int out_size)
{
    const float* x     = (const float*)d_in[0];
    const float* w_qkv = (const float*)d_in[1];
    const float* w_out = (const float*)d_in[2];
    float* y = (float*)d_out;

    static int configured = 0;
    if (!configured) {
        cudaFuncSetAttribute(k_qkv,   cudaFuncAttributeMaxDynamicSharedMemorySize, SMEM_DYN);
        cudaFuncSetAttribute(k_score, cudaFuncAttributeMaxDynamicSharedMemorySize, SMEM_DYN);
        cudaFuncSetAttribute(k_pv,    cudaFuncAttributeMaxDynamicSharedMemorySize, SMEM_DYN);
        cudaFuncSetAttribute(k_out,   cudaFuncAttributeMaxDynamicSharedMemorySize, SMEM_DYN);
        configured = 1;
    }

    k_qkv<<<dim3(C3 / 128, (BB * LL) / 128), 256, SMEM_DYN>>>(x, w_qkv);
    k_score<<<dim3(LL / 128, LL / 128, BB), 256, SMEM_DYN>>>();
    softmax_kernel<<<dim3(LL, BB), 256>>>();
    k_pv<<<dim3(CC / 128, LL / 128, BB), 256, SMEM_DYN>>>();
    k_out<<<dim3(CC / 128, (BB * LL) / 128), 256, SMEM_DYN>>>(w_out, y);
}

// round 6
// speedup vs baseline: 4.1592x; 1.2670x over previous
#include <cuda_runtime.h>
#include <math.h>
#include <stdint.h>

#define BB 4
#define LL 2048
#define CC 1024
#define C3 3072

// Scratch (device globals are the sanctioned scratch mechanism)
__device__ float g_qkv[(size_t)BB * LL * C3];   // 96 MB (tf32-rounded)
__device__ float g_attn[(size_t)BB * LL * LL];  // 64 MB (softmax out tf32-rounded)
__device__ float g_o[(size_t)BB * LL * CC];     // 32 MB (tf32-rounded)
__device__ float g_vt[(size_t)BB * CC * LL];    // 32 MB V transposed, K-major
__device__ float g_x[(size_t)BB * LL * CC];     // 32 MB x tf32-rounded
__device__ float g_wq[(size_t)C3 * CC];         // 12 MB w_qkv tf32-rounded
__device__ float g_wo[(size_t)CC * CC];         //  4 MB w_out tf32-rounded

// ---------------- helpers ----------------
__device__ __forceinline__ uint32_t smem_u32(const void* p) {
    uint32_t a;
    asm("{ .reg .u64 t; cvta.to.shared.u64 t, %1; cvt.u32.u64 %0, t; }" : "=r"(a) : "l"(p));
    return a;
}
__device__ __forceinline__ uint32_t f2tf(float f) {  // fp32 -> tf32, round-to-nearest
    uint32_t r;
    asm("cvt.rna.tf32.f32 %0, %1;" : "=r"(r) : "f"(f));
    return r;
}
__device__ __forceinline__ uint32_t swz(uint32_t off) {  // 128B-row XOR swizzle
    return off ^ ((off >> 3) & 0x70);
}
__device__ __forceinline__ void ldsm4(uint32_t (&r)[4], uint32_t addr) {
    asm volatile("ldmatrix.sync.aligned.m8n8.x4.shared.b16 {%0,%1,%2,%3}, [%4];"
                 : "=r"(r[0]), "=r"(r[1]), "=r"(r[2]), "=r"(r[3]) : "r"(addr));
}
__device__ __forceinline__ void mma_tf32(float (&d)[4], const uint32_t (&a)[4],
                                         const uint32_t b0, const uint32_t b1) {
    asm volatile("mma.sync.aligned.m16n8k8.row.col.f32.tf32.tf32.f32 "
                 "{%0,%1,%2,%3}, {%4,%5,%6,%7}, {%8,%9}, {%0,%1,%2,%3};"
                 : "+f"(d[0]), "+f"(d[1]), "+f"(d[2]), "+f"(d[3])
                 : "r"(a[0]), "r"(a[1]), "r"(a[2]), "r"(a[3]), "r"(b0), "r"(b1));
}
#define CPA16(dst, src) \
    asm volatile("cp.async.cg.shared.global [%0], [%1], 16;" :: "r"(dst), "l"(src) : "memory")
#define CPA_COMMIT() asm volatile("cp.async.commit_group;" ::: "memory")
template <int N>
__device__ __forceinline__ void cpa_wait() {
    asm volatile("cp.async.wait_group %0;" :: "n"(N) : "memory");
}

// Tile: 128 rows x 32 k-floats = 128B rows, XOR-swizzled (conflict-free ldmatrix + cp.async).
// Stage = A tile (16KB) + B tile (16KB). 3 stages = 96KB dynamic smem.
#define TILE_BYTES  16384
#define STAGE_BYTES 32768
#define NSTAGE      3
#define SMEM_DYN    (NSTAGE * STAGE_BYTES)

// ---------------- tf32 mma.sync GEMM (both operands K-major, cp.async 3-stage) ----------------
// C[m0..+128, n0..+128] = scale * A(rows m0.., lda) . B(rows n0.., ldb)^T
// Inputs MUST be tf32-pre-rounded fp32. Ksz multiple of 32, >= 64.
// MASK: causal -inf where col > row. ROUND: tf32-round outputs (for downstream GEMMs).
template <bool MASK, bool ROUND>
__device__ __forceinline__ void tc_gemm(const float* __restrict__ A, int lda,
                                        const float* __restrict__ B, int ldb,
                                        float* __restrict__ C, int ldc,
                                        int Ksz, int m0, int n0, float scale)
{
    extern __shared__ __align__(128) float dsm[];
    const uint32_t sb = smem_u32(dsm);

    const int tid = threadIdx.x;
    const int ln = tid & 31, wid = tid >> 5;
    const int wm = wid >> 2, wn = wid & 3;     // warp tile origin (wm*64, wn*32)
    const int gid = ln >> 2, tig = ln & 3;

    // cp.async coords: thread covers rows rA, rA+64; 16B cols cA, cA+4
    const int rA = tid >> 2, cA = tid & 3;

    // ldmatrix invariant pieces
    const int rowAf = wm * 64 + (ln & 7) + ((ln >> 3) & 1) * 8;
    const int colA16 = ln >> 4;
    const int rowBf = wn * 32 + (ln & 7) + ((ln >> 4) & 1) * 8;
    const int colB16 = (ln >> 3) & 1;

    float acc[4][4][4];
#pragma unroll
    for (int i = 0; i < 4; i++)
#pragma unroll
        for (int j = 0; j < 4; j++)
#pragma unroll
            for (int e = 0; e < 4; e++) acc[i][j][e] = 0.f;

    const int nch = Ksz >> 5;   // k32 chunks (nch >= 2 for all call sites)

    auto issue_chunk = [&](int kc, int s) {
        const uint32_t st = sb + (uint32_t)(s * STAGE_BYTES);
        const float* gA = A + (size_t)(m0 + rA) * lda + kc * 32;
        const float* gB = B + (size_t)(n0 + rA) * ldb + kc * 32;
#pragma unroll
        for (int h = 0; h < 2; h++) {
            const int c16 = cA + h * 4;
            CPA16(st + swz((uint32_t)(rA * 128 + c16 * 16)), gA + c16 * 4);
            CPA16(st + swz((uint32_t)((rA + 64) * 128 + c16 * 16)), gA + (size_t)64 * lda + c16 * 4);
            CPA16(st + TILE_BYTES + swz((uint32_t)(rA * 128 + c16 * 16)), gB + c16 * 4);
            CPA16(st + TILE_BYTES + swz((uint32_t)((rA + 64) * 128 + c16 * 16)), gB + (size_t)64 * ldb + c16 * 4);
        }
        CPA_COMMIT();
    };

    auto compute_k8 = [&](int s, int q) {
        const uint32_t aB = sb + (uint32_t)(s * STAGE_BYTES);
        const uint32_t bB = aB + TILE_BYTES;
        uint32_t af[4][4];
#pragma unroll
        for (int i = 0; i < 4; i++)
            ldsm4(af[i], aB + swz((uint32_t)((rowAf + i * 16) * 128 + q * 32 + colA16 * 16)));
        uint32_t bf[4][2];
#pragma unroll
        for (int p = 0; p < 2; ++p) {
            uint32_t qq[4];
            ldsm4(qq, bB + swz((uint32_t)((rowBf + p * 16) * 128 + q * 32 + colB16 * 16)));
            bf[2 * p][0] = qq[0]; bf[2 * p][1] = qq[1];
            bf[2 * p + 1][0] = qq[2]; bf[2 * p + 1][1] = qq[3];
        }
#pragma unroll
        for (int i = 0; i < 4; i++)
#pragma unroll
            for (int j = 0; j < 4; j++)
                mma_tf32(acc[i][j], af[i], bf[j][0], bf[j][1]);
    };

    // prologue: stages 0,1
    issue_chunk(0, 0);
    issue_chunk(1, 1);

    int s = 0;
    for (int c = 0; c < nch; ++c) {
        cpa_wait<1>();          // chunk c's group complete (empty tail commits keep this valid)
        __syncthreads();
        if (c + 2 < nch) {
            int s2 = s + 2;
            if (s2 >= NSTAGE) s2 -= NSTAGE;   // FIXED: proper modular wrap (was OOB for s=2)
            issue_chunk(c + 2, s2);
        } else {
            CPA_COMMIT();       // keep group accounting uniform
        }
#pragma unroll
        for (int q = 0; q < 4; ++q) compute_k8(s, q);
        __syncthreads();        // all consumers done before stage s is overwritten
        if (++s == NSTAGE) s = 0;
    }

    // ---- epilogue: registers -> gmem (float2 stores) ----
#pragma unroll
    for (int i = 0; i < 4; i++) {
        const int row0 = m0 + wm * 64 + i * 16 + gid;
#pragma unroll
        for (int j = 0; j < 4; j++) {
            const int col = n0 + wn * 32 + j * 8 + 2 * tig;
            float2 v0, v1;
            v0.x = acc[i][j][0] * scale; v0.y = acc[i][j][1] * scale;
            v1.x = acc[i][j][2] * scale; v1.y = acc[i][j][3] * scale;
            if (MASK) {
                if (col > row0)         v0.x = -INFINITY;
                if (col + 1 > row0)     v0.y = -INFINITY;
                if (col > row0 + 8)     v1.x = -INFINITY;
                if (col + 1 > row0 + 8) v1.y = -INFINITY;
            }
            if (ROUND) {
                v0.x = __uint_as_float(f2tf(v0.x)); v0.y = __uint_as_float(f2tf(v0.y));
                v1.x = __uint_as_float(f2tf(v1.x)); v1.y = __uint_as_float(f2tf(v1.y));
            }
            *(float2*)(C + (size_t)row0 * ldc + col) = v0;
            *(float2*)(C + (size_t)(row0 + 8) * ldc + col) = v1;
        }
    }
}

// ---------------- small prep kernels ----------------
__global__ void __launch_bounds__(256) k_round(const float* __restrict__ in,
                                               float* __restrict__ out, int n4) {
    int i = blockIdx.x * 256 + threadIdx.x;
    int stride = gridDim.x * 256;
    for (; i < n4; i += stride) {
        float4 v = ((const float4*)in)[i];
        v.x = __uint_as_float(f2tf(v.x)); v.y = __uint_as_float(f2tf(v.y));
        v.z = __uint_as_float(f2tf(v.z)); v.w = __uint_as_float(f2tf(v.w));
        ((float4*)out)[i] = v;
    }
}

// V slice of g_qkv [b][l][2048+c] -> g_vt [b][c][l]
__global__ void __launch_bounds__(256) k_transpose_v() {
    __shared__ float tile[32][33];
    const int b = blockIdx.z;
    const int c0 = blockIdx.x * 32, l0 = blockIdx.y * 32;
    const int tx = threadIdx.x, ty = threadIdx.y;
#pragma unroll
    for (int i = 0; i < 4; i++) {
        int l = l0 + ty + i * 8;
        tile[ty + i * 8][tx] = g_qkv[((size_t)b * LL + l) * C3 + 2 * CC + c0 + tx];
    }
    __syncthreads();
#pragma unroll
    for (int i = 0; i < 4; i++) {
        int c = c0 + ty + i * 8;
        g_vt[((size_t)b * CC + c) * LL + l0 + tx] = tile[tx][ty + i * 8];
    }
}

// ---------------- stage kernels ----------------
__global__ void __launch_bounds__(256, 2) k_qkv() {
    tc_gemm<false, true>(g_x, CC, g_wq, CC, g_qkv, C3, CC,
                         blockIdx.y * 128, blockIdx.x * 128, 1.f);
}

__global__ void __launch_bounds__(256, 2) k_score() {
    const int b = blockIdx.z;
    const int m0 = blockIdx.y * 128, n0 = blockIdx.x * 128;
    if (n0 > m0) return;  // fully-masked block: never written, never read by softmax
    const float* Q = g_qkv + (size_t)b * LL * C3;
    tc_gemm<true, false>(Q, C3, Q + CC, C3, g_attn + (size_t)b * LL * LL, LL, CC,
                         m0, n0, 0.03125f);
}

__global__ void __launch_bounds__(256) softmax_kernel() {
    int q = blockIdx.x, b = blockIdx.y;
    float* row = g_attn + ((size_t)b * LL + q) * LL;
    int kend = ((q >> 7) + 1) << 7;
    int tid = threadIdx.x;

    float v[8];
#pragma unroll
    for (int i = 0; i < 8; i++) {
        int k = tid + i * 256;
        v[i] = (k < kend) ? row[k] : -INFINITY;
    }
    float m = -INFINITY;
#pragma unroll
    for (int i = 0; i < 8; i++) m = fmaxf(m, v[i]);

    __shared__ float sred[8];
#pragma unroll
    for (int o = 16; o; o >>= 1) m = fmaxf(m, __shfl_xor_sync(0xffffffffu, m, o));
    if ((tid & 31) == 0) sred[tid >> 5] = m;
    __syncthreads();
    if (tid < 32) {
        float x = (tid < 8) ? sred[tid] : -INFINITY;
#pragma unroll
        for (int o = 4; o; o >>= 1) x = fmaxf(x, __shfl_xor_sync(0xffffffffu, x, o));
        if (tid == 0) sred[0] = x;
    }
    __syncthreads();
    m = sred[0];
    __syncthreads();

    float s = 0.f;
#pragma unroll
    for (int i = 0; i < 8; i++) { v[i] = expf(v[i] - m); s += v[i]; }
#pragma unroll
    for (int o = 16; o; o >>= 1) s += __shfl_xor_sync(0xffffffffu, s, o);
    if ((tid & 31) == 0) sred[tid >> 5] = s;
    __syncthreads();
    if (tid < 32) {
        float x = (tid < 8) ? sred[tid] : 0.f;
#pragma unroll
        for (int o = 4; o; o >>= 1) x += __shfl_xor_sync(0xffffffffu, x, o);
        if (tid == 0) sred[0] = x;
    }
    __syncthreads();
    float inv = 1.0f / sred[0];
#pragma unroll
    for (int i = 0; i < 8; i++) {
        int k = tid + i * 256;
        if (k < kend) row[k] = __uint_as_float(f2tf(v[i] * inv));  // pre-round for pv
    }
}

__global__ void __launch_bounds__(256, 2) k_pv() {
    const int b = blockIdx.z;
    // longest-K tiles first (K = m0 + 128 grows with m0)
    const int by = gridDim.y - 1 - blockIdx.y;
    const int m0 = by * 128, n0 = blockIdx.x * 128;
    const float* P = g_attn + (size_t)b * LL * LL;
    const float* Vt = g_vt + (size_t)b * CC * LL;
    tc_gemm<false, true>(P, LL, Vt, LL, g_o + (size_t)b * LL * CC, CC,
                         m0 + 128 /* causal K truncation */, m0, n0, 1.f);
}

__global__ void __launch_bounds__(256, 2) k_out(float* __restrict__ y) {
    tc_gemm<false, false>(g_o, CC, g_wo, CC, y, CC, CC,
                          blockIdx.y * 128, blockIdx.x * 128, 1.f);
}

extern "C" void kernel_launch(void* const* d_in, const int* in_sizes, int n_in,
                              void* d_out, int out_size)
{
    const float* x     = (const float*)d_in[0];
    const float* w_qkv = (const float*)d_in[1];
    const float* w_out = (const float*)d_in[2];
    float* y = (float*)d_out;

    static int configured = 0;
    if (!configured) {
        cudaFuncSetAttribute(k_qkv,   cudaFuncAttributeMaxDynamicSharedMemorySize, SMEM_DYN);
        cudaFuncSetAttribute(k_score, cudaFuncAttributeMaxDynamicSharedMemorySize, SMEM_DYN);
        cudaFuncSetAttribute(k_pv,    cudaFuncAttributeMaxDynamicSharedMemorySize, SMEM_DYN);
        cudaFuncSetAttribute(k_out,   cudaFuncAttributeMaxDynamicSharedMemorySize, SMEM_DYN);
        configured = 1;
    }

    float* gx;  cudaGetSymbolAddress((void**)&gx,  g_x);
    float* gwq; cudaGetSymbolAddress((void**)&gwq, g_wq);
    float* gwo; cudaGetSymbolAddress((void**)&gwo, g_wo);

    k_round<<<512, 256>>>(x,     gx,  (BB * LL * CC) / 4);
    k_round<<<512, 256>>>(w_qkv, gwq, (C3 * CC) / 4);
    k_round<<<256, 256>>>(w_out, gwo, (CC * CC) / 4);

    k_qkv<<<dim3(C3 / 128, (BB * LL) / 128), 256, SMEM_DYN>>>();
    k_transpose_v<<<dim3(CC / 32, LL / 32, BB), dim3(32, 8)>>>();
    k_score<<<dim3(LL / 128, LL / 128, BB), 256, SMEM_DYN>>>();
    softmax_kernel<<<dim3(LL, BB), 256>>>();
    k_pv<<<dim3(CC / 128, LL / 128, BB), 256, SMEM_DYN>>>();
    k_out<<<dim3(CC / 128, (BB * LL) / 128), 256, SMEM_DYN>>>(y);
}